// round 2
// baseline (speedup 1.0000x reference)
#include <cuda_runtime.h>
#include <cstdint>

// ---------------------------------------------------------------------------
// MipmappedTexture: 8-level mip pyramid of a (16, 512, 512) f32 texture,
// sampled at 1M (u,v) points with trilinear (bilinear x level-lerp) filtering.
//
// Strategy:
//   Kernel 1: transpose base texture (C,H,W) -> channel-last (H,W,C) level 0.
//   Kernel 2: build levels 1..7 directly from level 0 (4-tap bilinear,
//             align_corners=False resize semantics).
//   Kernel 3: 4 threads per query; each thread owns 4 channels (float4).
//             Every tap is one coalesced 64B access (4 lanes x 16B).
// Pyramid lives in a __device__ global (no allocation).
// ---------------------------------------------------------------------------

#define NUM_LEVELS 8
#define BASE_W     512
#define CHANNELS   16

// total pixels over all levels: sum (512>>i)^2, i=0..7
#define TOTAL_PIX  349520
#define L0_PIX     (512*512)          // 262144
#define MIP_PIX    (TOTAL_PIX - L0_PIX) // 87376

__device__ float g_pyr[(size_t)TOTAL_PIX * CHANNELS];  // ~22.4 MB, channel-last

// pixel offset of level l: (2^20 - 2^(20-2l)) / 3
__device__ __forceinline__ int lvl_off(int l) {
    return (1048576 - (1048576 >> (2 * l))) / 3;
}

// ------------------------- Kernel 1: transpose -----------------------------
__global__ void k_transpose(const float* __restrict__ tex) {
    int pix = blockIdx.x * blockDim.x + threadIdx.x;   // 0..262143
    float v[CHANNELS];
#pragma unroll
    for (int c = 0; c < CHANNELS; ++c)
        v[c] = __ldg(&tex[(size_t)c * L0_PIX + pix]);  // coalesced per c
    float4* dst = reinterpret_cast<float4*>(g_pyr + (size_t)pix * CHANNELS);
#pragma unroll
    for (int i = 0; i < 4; ++i)
        dst[i] = make_float4(v[4*i], v[4*i+1], v[4*i+2], v[4*i+3]);
}

// ------------------------- Kernel 2: build mips ----------------------------
// Levels 1..7, each output pixel = 4-tap bilinear of level 0
// (align_corners=False resize: src = (dst+0.5)*scale - 0.5, clamped).
__global__ void k_mips() {
    int idx = blockIdx.x * blockDim.x + threadIdx.x;
    if (idx >= MIP_PIX) return;

    // find level
    int l = 1, rem = idx;
#pragma unroll
    for (int i = 1; i < NUM_LEVELS; ++i) {
        int n = (BASE_W >> i) * (BASE_W >> i);
        if (rem < n) { l = i; break; }
        rem -= n;
    }
    int w = BASE_W >> l;
    int y = rem / w;
    int x = rem - y * w;
    float s = (float)(1 << l);

    float sy = (y + 0.5f) * s - 0.5f; sy = fmaxf(sy, 0.0f);
    float sx = (x + 0.5f) * s - 0.5f; sx = fmaxf(sx, 0.0f);
    int y0 = (int)sy; y0 = min(y0, BASE_W - 1);
    int x0 = (int)sx; x0 = min(x0, BASE_W - 1);
    int y1 = min(y0 + 1, BASE_W - 1);
    int x1 = min(x0 + 1, BASE_W - 1);
    float ty = sy - (float)y0;
    float tx = sx - (float)x0;

    float w00 = (1.0f - tx) * (1.0f - ty);
    float w01 = tx * (1.0f - ty);
    float w10 = (1.0f - tx) * ty;
    float w11 = tx * ty;

    const float4* t00 = reinterpret_cast<const float4*>(g_pyr + (size_t)(y0 * BASE_W + x0) * CHANNELS);
    const float4* t01 = reinterpret_cast<const float4*>(g_pyr + (size_t)(y0 * BASE_W + x1) * CHANNELS);
    const float4* t10 = reinterpret_cast<const float4*>(g_pyr + (size_t)(y1 * BASE_W + x0) * CHANNELS);
    const float4* t11 = reinterpret_cast<const float4*>(g_pyr + (size_t)(y1 * BASE_W + x1) * CHANNELS);

    float4* dst = reinterpret_cast<float4*>(g_pyr + (size_t)(lvl_off(l) + rem) * CHANNELS);
#pragma unroll
    for (int i = 0; i < 4; ++i) {
        float4 a = t00[i], b = t01[i], c = t10[i], d = t11[i];
        float4 r;
        r.x = a.x * w00 + b.x * w01 + c.x * w10 + d.x * w11;
        r.y = a.y * w00 + b.y * w01 + c.y * w10 + d.y * w11;
        r.z = a.z * w00 + b.z * w01 + c.z * w10 + d.z * w11;
        r.w = a.w * w00 + b.w * w01 + c.w * w10 + d.w * w11;
        dst[i] = r;
    }
}

// ------------------------- Kernel 3: sample --------------------------------
// grid_sample, align_corners=True, border padding:
//   x = clamp(u*(w-1), 0, w-1)
__device__ __forceinline__ float4 sample_level(int l, float u, float v, int cg) {
    int w = BASE_W >> l;
    float fw = (float)(w - 1);
    float x = fminf(fmaxf(u * fw, 0.0f), fw);
    float y = fminf(fmaxf(v * fw, 0.0f), fw);
    int x0 = (int)x;
    int y0 = (int)y;
    int x1 = min(x0 + 1, w - 1);
    int y1 = min(y0 + 1, w - 1);
    float fx = x - (float)x0;
    float fy = y - (float)y0;

    const float* base = g_pyr + (size_t)lvl_off(l) * CHANNELS + cg * 4;
    const float4 a = *reinterpret_cast<const float4*>(base + (size_t)(y0 * w + x0) * CHANNELS);
    const float4 b = *reinterpret_cast<const float4*>(base + (size_t)(y0 * w + x1) * CHANNELS);
    const float4 c = *reinterpret_cast<const float4*>(base + (size_t)(y1 * w + x0) * CHANNELS);
    const float4 d = *reinterpret_cast<const float4*>(base + (size_t)(y1 * w + x1) * CHANNELS);

    float w00 = (1.0f - fx) * (1.0f - fy);
    float w01 = fx * (1.0f - fy);
    float w10 = (1.0f - fx) * fy;
    float w11 = fx * fy;

    float4 r;
    r.x = a.x * w00 + b.x * w01 + c.x * w10 + d.x * w11;
    r.y = a.y * w00 + b.y * w01 + c.y * w10 + d.y * w11;
    r.z = a.z * w00 + b.z * w01 + c.z * w10 + d.z * w11;
    r.w = a.w * w00 + b.w * w01 + c.w * w10 + d.w * w11;
    return r;
}

__global__ void k_sample(const float2* __restrict__ uv,
                         const float* __restrict__ p,
                         float* __restrict__ out, int n) {
    int tid = blockIdx.x * blockDim.x + threadIdx.x;
    int q = tid >> 2;
    if (q >= n) return;
    int cg = tid & 3;

    float2 uvq = __ldg(&uv[q]);
    float lf = __ldg(&p[q]) * (float)(NUM_LEVELS - 1);
    int l0 = min((int)lf, NUM_LEVELS - 1);
    int l1 = min(l0 + 1, NUM_LEVELS - 1);
    float alpha = lf - (float)l0;

    float4 s0 = sample_level(l0, uvq.x, uvq.y, cg);
    float4 s1 = sample_level(l1, uvq.x, uvq.y, cg);

    float4 r;
    r.x = s0.x + alpha * (s1.x - s0.x);
    r.y = s0.y + alpha * (s1.y - s0.y);
    r.z = s0.z + alpha * (s1.z - s0.z);
    r.w = s0.w + alpha * (s1.w - s0.w);

    reinterpret_cast<float4*>(out + (size_t)q * CHANNELS)[cg] = r;
}

// ---------------------------------------------------------------------------
extern "C" void kernel_launch(void* const* d_in, const int* in_sizes, int n_in,
                              void* d_out, int out_size) {
    const float* uv  = (const float*)d_in[0];   // (N, 2)
    const float* p   = (const float*)d_in[1];   // (N,)
    const float* tex = (const float*)d_in[2];   // (1, 16, 512, 512)
    float* out = (float*)d_out;                 // (N, 16)
    int n = in_sizes[1];                        // N queries

    k_transpose<<<L0_PIX / 256, 256>>>(tex);
    k_mips<<<(MIP_PIX + 255) / 256, 256>>>();
    int threads = n * 4;
    k_sample<<<(threads + 255) / 256, 256>>>(
        (const float2*)uv, p, out, n);
}

// round 3
// speedup vs baseline: 1.3275x; 1.3275x over previous
#include <cuda_runtime.h>
#include <cuda_fp16.h>
#include <cstdint>

// ---------------------------------------------------------------------------
// Mipmapped texture sampling, fp16 pyramid edition.
//   Pyramid stored channel-last (H,W,C) in fp16: 32 B per texel.
//   Kernel 1: transpose (C,H,W) f32 -> (H,W,C) f16 level 0.
//   Kernel 2: levels 1..7 from level 0 (align_corners=False bilinear resize).
//   Kernel 3: 2 threads/query, 8 channels each; every tap = one 16 B uint4.
// ---------------------------------------------------------------------------

#define NUM_LEVELS 8
#define BASE_W     512
#define CHANNELS   16

#define TOTAL_PIX  349520               // sum (512>>i)^2
#define L0_PIX     (512*512)
#define MIP_PIX    (TOTAL_PIX - L0_PIX)

__device__ __half g_pyr[(size_t)TOTAL_PIX * CHANNELS];   // ~11.2 MB

__device__ __forceinline__ int lvl_off(int l) {
    return (1048576 - (1048576 >> (2 * l))) / 3;
}

// ------------------------- Kernel 1: transpose + quantize ------------------
__global__ void k_transpose(const float* __restrict__ tex) {
    int pix = blockIdx.x * blockDim.x + threadIdx.x;   // 0..262143
    float v[CHANNELS];
#pragma unroll
    for (int c = 0; c < CHANNELS; ++c)
        v[c] = __ldg(&tex[(size_t)c * L0_PIX + pix]);
    __half2 h[8];
#pragma unroll
    for (int i = 0; i < 8; ++i)
        h[i] = __floats2half2_rn(v[2*i], v[2*i+1]);
    uint4* dst = reinterpret_cast<uint4*>(g_pyr + (size_t)pix * CHANNELS);
    dst[0] = *reinterpret_cast<uint4*>(&h[0]);
    dst[1] = *reinterpret_cast<uint4*>(&h[4]);
}

// ------------------------- tap helpers -------------------------------------
// Load one 32B fp16 texel (16 channels) and convert to 16 floats.
__device__ __forceinline__ void load_texel16(const __half* ptr, float* f) {
    const uint4* p4 = reinterpret_cast<const uint4*>(ptr);
    uint4 a = p4[0], b = p4[1];
    const __half2* ha = reinterpret_cast<const __half2*>(&a);
    const __half2* hb = reinterpret_cast<const __half2*>(&b);
#pragma unroll
    for (int i = 0; i < 4; ++i) {
        float2 t = __half22float2(ha[i]);
        f[2*i] = t.x; f[2*i+1] = t.y;
    }
#pragma unroll
    for (int i = 0; i < 4; ++i) {
        float2 t = __half22float2(hb[i]);
        f[8+2*i] = t.x; f[8+2*i+1] = t.y;
    }
}

// ------------------------- Kernel 2: build mips ----------------------------
__global__ void k_mips() {
    int idx = blockIdx.x * blockDim.x + threadIdx.x;
    if (idx >= MIP_PIX) return;

    int l = 1, rem = idx;
#pragma unroll
    for (int i = 1; i < NUM_LEVELS; ++i) {
        int n = (BASE_W >> i) * (BASE_W >> i);
        if (rem < n) { l = i; break; }
        rem -= n;
    }
    int w = BASE_W >> l;
    int y = rem / w;
    int x = rem - y * w;
    float s = (float)(1 << l);

    float sy = fmaxf((y + 0.5f) * s - 0.5f, 0.0f);
    float sx = fmaxf((x + 0.5f) * s - 0.5f, 0.0f);
    int y0 = min((int)sy, BASE_W - 1);
    int x0 = min((int)sx, BASE_W - 1);
    int y1 = min(y0 + 1, BASE_W - 1);
    int x1 = min(x0 + 1, BASE_W - 1);
    float ty = sy - (float)y0;
    float tx = sx - (float)x0;

    float w00 = (1.0f - tx) * (1.0f - ty);
    float w01 = tx * (1.0f - ty);
    float w10 = (1.0f - tx) * ty;
    float w11 = tx * ty;

    float a[16], b[16], c[16], d[16];
    load_texel16(g_pyr + (size_t)(y0 * BASE_W + x0) * CHANNELS, a);
    load_texel16(g_pyr + (size_t)(y0 * BASE_W + x1) * CHANNELS, b);
    load_texel16(g_pyr + (size_t)(y1 * BASE_W + x0) * CHANNELS, c);
    load_texel16(g_pyr + (size_t)(y1 * BASE_W + x1) * CHANNELS, d);

    __half2 h[8];
#pragma unroll
    for (int i = 0; i < 8; ++i) {
        float r0 = a[2*i]   * w00 + b[2*i]   * w01 + c[2*i]   * w10 + d[2*i]   * w11;
        float r1 = a[2*i+1] * w00 + b[2*i+1] * w01 + c[2*i+1] * w10 + d[2*i+1] * w11;
        h[i] = __floats2half2_rn(r0, r1);
    }
    uint4* dst = reinterpret_cast<uint4*>(g_pyr + (size_t)(lvl_off(l) + rem) * CHANNELS);
    dst[0] = *reinterpret_cast<uint4*>(&h[0]);
    dst[1] = *reinterpret_cast<uint4*>(&h[4]);
}

// ------------------------- Kernel 3: sample --------------------------------
// 2 threads per query; cg in {0,1} selects 8 channels (one uint4 per tap).
// grid_sample: align_corners=True, border padding.
__device__ __forceinline__ void sample_level8(int l, float u, float v, int cg,
                                              float* r) {
    int w = BASE_W >> l;
    float fw = (float)(w - 1);
    float x = fminf(fmaxf(u * fw, 0.0f), fw);
    float y = fminf(fmaxf(v * fw, 0.0f), fw);
    int x0 = (int)x;
    int y0 = (int)y;
    int x1 = min(x0 + 1, w - 1);
    int y1 = min(y0 + 1, w - 1);
    float fx = x - (float)x0;
    float fy = y - (float)y0;

    // texel stride = 16 halves = 32 B = 2 uint4; cg picks the half-texel
    const uint4* base = reinterpret_cast<const uint4*>(
        g_pyr + (size_t)lvl_off(l) * CHANNELS) + cg;

    uint4 ra = base[(size_t)(y0 * w + x0) * 2];
    uint4 rb = base[(size_t)(y0 * w + x1) * 2];
    uint4 rc = base[(size_t)(y1 * w + x0) * 2];
    uint4 rd = base[(size_t)(y1 * w + x1) * 2];

    float w00 = (1.0f - fx) * (1.0f - fy);
    float w01 = fx * (1.0f - fy);
    float w10 = (1.0f - fx) * fy;
    float w11 = fx * fy;

    const __half2* ha = reinterpret_cast<const __half2*>(&ra);
    const __half2* hb = reinterpret_cast<const __half2*>(&rb);
    const __half2* hc = reinterpret_cast<const __half2*>(&rc);
    const __half2* hd = reinterpret_cast<const __half2*>(&rd);
#pragma unroll
    for (int i = 0; i < 4; ++i) {
        float2 fa = __half22float2(ha[i]);
        float2 fb = __half22float2(hb[i]);
        float2 fc = __half22float2(hc[i]);
        float2 fd = __half22float2(hd[i]);
        r[2*i]   = fa.x * w00 + fb.x * w01 + fc.x * w10 + fd.x * w11;
        r[2*i+1] = fa.y * w00 + fb.y * w01 + fc.y * w10 + fd.y * w11;
    }
}

__global__ void k_sample(const float2* __restrict__ uv,
                         const float* __restrict__ p,
                         float* __restrict__ out, int n) {
    int tid = blockIdx.x * blockDim.x + threadIdx.x;
    int q = tid >> 1;
    if (q >= n) return;
    int cg = tid & 1;

    float2 uvq = __ldg(&uv[q]);
    float lf = __ldg(&p[q]) * (float)(NUM_LEVELS - 1);
    int l0 = min((int)lf, NUM_LEVELS - 1);
    int l1 = min(l0 + 1, NUM_LEVELS - 1);
    float alpha = lf - (float)l0;

    float s0[8], s1[8];
    sample_level8(l0, uvq.x, uvq.y, cg, s0);
    sample_level8(l1, uvq.x, uvq.y, cg, s1);

    float4 o0, o1;
    o0.x = s0[0] + alpha * (s1[0] - s0[0]);
    o0.y = s0[1] + alpha * (s1[1] - s0[1]);
    o0.z = s0[2] + alpha * (s1[2] - s0[2]);
    o0.w = s0[3] + alpha * (s1[3] - s0[3]);
    o1.x = s0[4] + alpha * (s1[4] - s0[4]);
    o1.y = s0[5] + alpha * (s1[5] - s0[5]);
    o1.z = s0[6] + alpha * (s1[6] - s0[6]);
    o1.w = s0[7] + alpha * (s1[7] - s0[7]);

    float4* dst = reinterpret_cast<float4*>(out + (size_t)q * CHANNELS) + cg * 2;
    dst[0] = o0;
    dst[1] = o1;
}

// ---------------------------------------------------------------------------
extern "C" void kernel_launch(void* const* d_in, const int* in_sizes, int n_in,
                              void* d_out, int out_size) {
    const float* uv  = (const float*)d_in[0];   // (N, 2)
    const float* p   = (const float*)d_in[1];   // (N,)
    const float* tex = (const float*)d_in[2];   // (1, 16, 512, 512)
    float* out = (float*)d_out;                 // (N, 16)
    int n = in_sizes[1];

    k_transpose<<<L0_PIX / 256, 256>>>(tex);
    k_mips<<<(MIP_PIX + 255) / 256, 256>>>();
    int threads = n * 2;
    k_sample<<<(threads + 255) / 256, 256>>>(
        (const float2*)uv, p, out, n);
}